// round 9
// baseline (speedup 1.0000x reference)
#include <cuda_runtime.h>
#include <cuda_fp16.h>
#include <cstdint>

#define N_NODES 10000
#define N_EDGES 640000
#define FDIM    128
#define NGRAPH  64
#define MAXD    192
#define PL      (N_NODES * 32)     // word offset of plane B within split arrays

// ---------------- device scratch (no allocation allowed) ----------------
__device__ int      g_deg[N_NODES];
__device__ float    g_dis[N_NODES];
__device__ int      g_bucket[N_NODES * MAXD];
// split-plane fp16 buffers: word i = half2. Plane A (feat 0..63): [node*32+w],
// plane B (feat 64..127): [PL + node*32+w]. 128B-aligned rows, 1 line per plane row.
__device__ __align__(128) unsigned g_g[N_NODES * 64];   // GEMM out, dis-prescaled
__device__ __align__(128) unsigned g_h[N_NODES * 64];   // agg out fp16 (layers 0,1)
__device__ float    g_hbuf[N_NODES * FDIM];             // agg out fp32 (layer 2)
__device__ int      g_starts[NGRAPH + 1];

// ---------------- one-pass bucket CSR: 8 edges per thread ----------------
__global__ void k_bucket8(const int* __restrict__ src, const int* __restrict__ dst) {
    int i = blockIdx.x * blockDim.x + threadIdx.x;
    if (i >= N_EDGES / 8) return;
    int4 s0 = ((const int4*)src)[i * 2 + 0];
    int4 s1 = ((const int4*)src)[i * 2 + 1];
    int4 d0 = ((const int4*)dst)[i * 2 + 0];
    int4 d1 = ((const int4*)dst)[i * 2 + 1];
    int p;
    p = atomicAdd(&g_deg[d0.x], 1); if (p < MAXD) g_bucket[d0.x * MAXD + p] = s0.x;
    p = atomicAdd(&g_deg[d0.y], 1); if (p < MAXD) g_bucket[d0.y * MAXD + p] = s0.y;
    p = atomicAdd(&g_deg[d0.z], 1); if (p < MAXD) g_bucket[d0.z * MAXD + p] = s0.z;
    p = atomicAdd(&g_deg[d0.w], 1); if (p < MAXD) g_bucket[d0.w * MAXD + p] = s0.w;
    p = atomicAdd(&g_deg[d1.x], 1); if (p < MAXD) g_bucket[d1.x * MAXD + p] = s1.x;
    p = atomicAdd(&g_deg[d1.y], 1); if (p < MAXD) g_bucket[d1.y * MAXD + p] = s1.y;
    p = atomicAdd(&g_deg[d1.z], 1); if (p < MAXD) g_bucket[d1.z * MAXD + p] = s1.z;
    p = atomicAdd(&g_deg[d1.w], 1); if (p < MAXD) g_bucket[d1.w * MAXD + p] = s1.w;
}

// dis = rsqrt(deg+1); also graph-boundary starts (batch is sorted)
__global__ void k_dis_starts(const int* __restrict__ batch) {
    int n = blockIdx.x * blockDim.x + threadIdx.x;
    if (n >= N_NODES) return;
    g_dis[n] = rsqrtf((float)g_deg[n] + 1.0f);
    int b1 = batch[n];
    if (n == 0) {
        for (int b = 0; b <= b1; b++) g_starts[b] = 0;
    } else {
        int b0 = batch[n - 1];
        for (int b = b0 + 1; b <= b1; b++) g_starts[b] = n;
    }
    if (n == N_NODES - 1) {
        for (int b = b1 + 1; b <= NGRAPH; b++) g_starts[b] = N_NODES;
    }
}

// ---------------- HMMA GEMM: split-plane OUT = half( dis[n] * (A[n] @ W) ) ----------------
__device__ __forceinline__ int swz_g(int row, int col8) {
    return row * FDIM + ((col8 ^ (row & 7)) << 3);
}
__device__ __forceinline__ int swz_h(int row, int col) {
    return row * FDIM + (((col >> 3) ^ (row & 7)) << 3) + (col & 7);
}

template<bool F32IN>
__global__ __launch_bounds__(512) void k_gemm(const void* __restrict__ Ap,
                                              const float* __restrict__ Wf,
                                              unsigned* __restrict__ OUT) {
    __shared__ __half Wsh[FDIM * FDIM];   // 32 KB
    __shared__ __half Ash[64 * FDIM];     // 16 KB
    int tid  = threadIdx.x;
    int lane = tid & 31;
    int warp = tid >> 5;
    int row0 = blockIdx.x * 64;

    #pragma unroll
    for (int i = 0; i < 8; i++) {
        int idx = tid + i * 512;
        int r   = idx >> 5;
        int c   = (idx & 31) * 4;
        float4 v = ((const float4*)Wf)[idx];
        uint2 h;
        *(__half2*)&h.x = __floats2half2_rn(v.x, v.y);
        *(__half2*)&h.y = __floats2half2_rn(v.z, v.w);
        *(uint2*)&Wsh[swz_h(r, c)] = h;
    }
    if (F32IN) {
        const float* A = (const float*)Ap;
        #pragma unroll
        for (int i = 0; i < 4; i++) {
            int idx = tid + i * 512;
            int r   = idx >> 5;
            int c   = (idx & 31) * 4;
            int gr  = row0 + r;
            float4 v = make_float4(0.f, 0.f, 0.f, 0.f);
            if (gr < N_NODES) v = *(const float4*)&A[gr * FDIM + c];
            uint2 h;
            *(__half2*)&h.x = __floats2half2_rn(v.x, v.y);
            *(__half2*)&h.y = __floats2half2_rn(v.z, v.w);
            *(uint2*)&Ash[swz_h(r, c)] = h;
        }
    } else {
        // A is split-plane fp16 (g_h layout)
        const unsigned* A = (const unsigned*)Ap;
        #pragma unroll
        for (int i = 0; i < 2; i++) {
            int idx = tid + i * 512;        // 0..1023
            int r   = idx >> 4;
            int c8  = idx & 15;             // uint4 chunk within row
            int gr  = row0 + r;
            uint4 v = make_uint4(0, 0, 0, 0);
            if (gr < N_NODES) {
                if (c8 < 8) v = ((const uint4*)A)[gr * 8 + c8];
                else        v = ((const uint4*)(A + PL))[gr * 8 + (c8 - 8)];
            }
            *(uint4*)&Ash[swz_g(r, c8)] = v;
        }
    }
    __syncthreads();

    int rw = (warp >> 2) * 16;
    int cw = (warp & 3) * 32;

    float acc[4][4];
    #pragma unroll
    for (int nt = 0; nt < 4; nt++)
        #pragma unroll
        for (int c = 0; c < 4; c++) acc[nt][c] = 0.f;

    int m  = lane >> 3;
    int l7 = lane & 7;

    #pragma unroll
    for (int kk = 0; kk < 8; kk++) {
        int k0 = kk * 16;
        uint32_t a0, a1, a2, a3;
        {
            int rl = rw + ((m & 1) << 3) + l7;
            int c8 = (k0 >> 3) + (m >> 1);
            uint32_t addr = (uint32_t)__cvta_generic_to_shared(&Ash[swz_g(rl, c8)]);
            asm volatile("ldmatrix.sync.aligned.m8n8.x4.shared.b16 {%0,%1,%2,%3}, [%4];"
                         : "=r"(a0), "=r"(a1), "=r"(a2), "=r"(a3) : "r"(addr));
        }
        #pragma unroll
        for (int nb = 0; nb < 2; nb++) {
            int n0 = cw + nb * 16;
            uint32_t b0, b1, b2, b3;
            {
                int rl = k0 + ((m & 1) << 3) + l7;
                int c8 = (n0 >> 3) + (m >> 1);
                uint32_t addr = (uint32_t)__cvta_generic_to_shared(&Wsh[swz_g(rl, c8)]);
                asm volatile("ldmatrix.sync.aligned.m8n8.x4.trans.shared.b16 {%0,%1,%2,%3}, [%4];"
                             : "=r"(b0), "=r"(b1), "=r"(b2), "=r"(b3) : "r"(addr));
            }
            float* c0 = acc[nb * 2];
            float* c1 = acc[nb * 2 + 1];
            asm volatile("mma.sync.aligned.m16n8k16.row.col.f32.f16.f16.f32 "
                         "{%0,%1,%2,%3}, {%4,%5,%6,%7}, {%8,%9}, {%0,%1,%2,%3};"
                         : "+f"(c0[0]), "+f"(c0[1]), "+f"(c0[2]), "+f"(c0[3])
                         : "r"(a0), "r"(a1), "r"(a2), "r"(a3), "r"(b0), "r"(b1));
            asm volatile("mma.sync.aligned.m16n8k16.row.col.f32.f16.f16.f32 "
                         "{%0,%1,%2,%3}, {%4,%5,%6,%7}, {%8,%9}, {%0,%1,%2,%3};"
                         : "+f"(c1[0]), "+f"(c1[1]), "+f"(c1[2]), "+f"(c1[3])
                         : "r"(a0), "r"(a1), "r"(a2), "r"(a3), "r"(b2), "r"(b3));
        }
    }

    // epilogue: scale by dis[row], store fp16 to split planes
    int gid  = lane >> 2;
    int tid4 = lane & 3;
    int r1 = row0 + rw + gid;
    int r2 = r1 + 8;
    float d1 = (r1 < N_NODES) ? g_dis[r1] : 0.f;
    float d2 = (r2 < N_NODES) ? g_dis[r2] : 0.f;
    #pragma unroll
    for (int nt = 0; nt < 4; nt++) {
        int col = cw + nt * 8 + tid4 * 2;           // even, 0..126
        int w   = (col < 64) ? (col >> 1) : (PL / 1 - PL + ((col - 64) >> 1) + PL); // see below
        // plane select without branch on address math clarity:
        int off = (col < 64) ? (col >> 1) : (PL + ((col - 64) >> 1));
        if (r1 < N_NODES) {
            __half2 h = __floats2half2_rn(acc[nt][0] * d1, acc[nt][1] * d1);
            OUT[r1 * 32 + off] = *(unsigned*)&h;
        }
        if (r2 < N_NODES) {
            __half2 h = __floats2half2_rn(acc[nt][2] * d2, acc[nt][3] * d2);
            OUT[r2 * 32 + off] = *(unsigned*)&h;
        }
        (void)w;
    }
}

// ---------------- aggregation: warp per node, split-plane 1-line gathers ----------------
#define H2(u) (*(__half2*)&(u))

__global__ __launch_bounds__(256) void k_agg(const unsigned* __restrict__ Gm,
                                             const float* __restrict__ bias,
                                             unsigned* __restrict__ H16,
                                             float* __restrict__ Hf,
                                             int relu) {
    int n    = (blockIdx.x * blockDim.x + threadIdx.x) >> 5;
    int lane = threadIdx.x & 31;
    if (n >= N_NODES) return;
    int deg = g_deg[n];
    if (deg > MAXD) deg = MAXD;
    const int* bk = g_bucket + n * MAXD;

    // lane covers features [2*lane, 2*lane+1] (plane A) and [64+2*lane, 65+2*lane] (plane B)
    unsigned sa = Gm[n * 32 + lane];
    unsigned sb = Gm[n * 32 + lane + PL];
    float2 t;
    t = __half22float2(H2(sa));
    float a0 = t.x, a1 = t.y;
    t = __half22float2(H2(sb));
    float b0f = t.x, b1f = t.y;

    int i = 0;
    for (; i + 8 <= deg; i += 8) {
        int4 i0 = *(const int4*)(bk + i);
        int4 i1 = *(const int4*)(bk + i + 4);
        int p0 = i0.x * 32 + lane, p1 = i0.y * 32 + lane;
        int p2 = i0.z * 32 + lane, p3 = i0.w * 32 + lane;
        int p4 = i1.x * 32 + lane, p5 = i1.y * 32 + lane;
        int p6 = i1.z * 32 + lane, p7 = i1.w * 32 + lane;
        unsigned va0 = Gm[p0], va1 = Gm[p1], va2 = Gm[p2], va3 = Gm[p3];
        unsigned va4 = Gm[p4], va5 = Gm[p5], va6 = Gm[p6], va7 = Gm[p7];
        unsigned vb0 = Gm[p0 + PL], vb1 = Gm[p1 + PL], vb2 = Gm[p2 + PL], vb3 = Gm[p3 + PL];
        unsigned vb4 = Gm[p4 + PL], vb5 = Gm[p5 + PL], vb6 = Gm[p6 + PL], vb7 = Gm[p7 + PL];
        __half2 sA = __hadd2(__hadd2(__hadd2(H2(va0), H2(va1)), __hadd2(H2(va2), H2(va3))),
                             __hadd2(__hadd2(H2(va4), H2(va5)), __hadd2(H2(va6), H2(va7))));
        __half2 sB = __hadd2(__hadd2(__hadd2(H2(vb0), H2(vb1)), __hadd2(H2(vb2), H2(vb3))),
                             __hadd2(__hadd2(H2(vb4), H2(vb5)), __hadd2(H2(vb6), H2(vb7))));
        t = __half22float2(sA); a0 += t.x; a1 += t.y;
        t = __half22float2(sB); b0f += t.x; b1f += t.y;
    }
    for (; i + 4 <= deg; i += 4) {
        int4 i0 = *(const int4*)(bk + i);
        int p0 = i0.x * 32 + lane, p1 = i0.y * 32 + lane;
        int p2 = i0.z * 32 + lane, p3 = i0.w * 32 + lane;
        unsigned va0 = Gm[p0], va1 = Gm[p1], va2 = Gm[p2], va3 = Gm[p3];
        unsigned vb0 = Gm[p0 + PL], vb1 = Gm[p1 + PL], vb2 = Gm[p2 + PL], vb3 = Gm[p3 + PL];
        __half2 sA = __hadd2(__hadd2(H2(va0), H2(va1)), __hadd2(H2(va2), H2(va3)));
        __half2 sB = __hadd2(__hadd2(H2(vb0), H2(vb1)), __hadd2(H2(vb2), H2(vb3)));
        t = __half22float2(sA); a0 += t.x; a1 += t.y;
        t = __half22float2(sB); b0f += t.x; b1f += t.y;
    }
    for (; i < deg; i++) {
        int p = bk[i] * 32 + lane;
        unsigned va = Gm[p];
        unsigned vb = Gm[p + PL];
        t = __half22float2(H2(va)); a0 += t.x; a1 += t.y;
        t = __half22float2(H2(vb)); b0f += t.x; b1f += t.y;
    }

    float d = g_dis[n];
    float2 biasA = ((const float2*)bias)[lane];
    float2 biasB = ((const float2*)bias)[lane + 32];
    float o0 = d * a0  + biasA.x;
    float o1 = d * a1  + biasA.y;
    float o2 = d * b0f + biasB.x;
    float o3 = d * b1f + biasB.y;
    if (relu) {
        o0 = fmaxf(o0, 0.f); o1 = fmaxf(o1, 0.f);
        o2 = fmaxf(o2, 0.f); o3 = fmaxf(o3, 0.f);
        __half2 hA = __floats2half2_rn(o0, o1);
        __half2 hB = __floats2half2_rn(o2, o3);
        H16[n * 32 + lane]      = *(unsigned*)&hA;
        H16[n * 32 + lane + PL] = *(unsigned*)&hB;
    } else {
        ((float2*)Hf)[n * 64 + lane]      = make_float2(o0, o1);
        ((float2*)Hf)[n * 64 + 32 + lane] = make_float2(o2, o3);
    }
}

// ---------------- mean pool: one block per graph, 4 warps split rows ----------------
__global__ __launch_bounds__(128) void k_pool(const float* __restrict__ H,
                                              float* __restrict__ out) {
    __shared__ float red[4][FDIM];
    int g    = blockIdx.x;
    int lane = threadIdx.x & 31;
    int warp = threadIdx.x >> 5;
    int s = g_starts[g];
    int e = g_starts[g + 1];
    float4 acc = make_float4(0.f, 0.f, 0.f, 0.f);
    for (int n = s + warp; n < e; n += 4) {
        float4 v = ((const float4*)H)[n * 32 + lane];
        acc.x += v.x; acc.y += v.y; acc.z += v.z; acc.w += v.w;
    }
    *(float4*)&red[warp][lane * 4] = acc;
    __syncthreads();
    int t = threadIdx.x;
    float sum = red[0][t] + red[1][t] + red[2][t] + red[3][t];
    float cnt = (float)(e - s);
    out[g * FDIM + t] = sum / fmaxf(cnt, 1.0f);
}

// ---------------- launch ----------------
extern "C" void kernel_launch(void* const* d_in, const int* in_sizes, int n_in,
                              void* d_out, int out_size) {
    const float* x     = (const float*)d_in[0];
    const int*   ei    = (const int*)d_in[1];
    const int*   batch = (const int*)d_in[2];
    const float* W0    = (const float*)d_in[3];
    const float* b0    = (const float*)d_in[4];
    const float* W1    = (const float*)d_in[5];
    const float* b1    = (const float*)d_in[6];
    const float* W2    = (const float*)d_in[7];
    const float* b2    = (const float*)d_in[8];
    float* out = (float*)d_out;

    const int* src = ei;
    const int* dst = ei + N_EDGES;

    int*      dg;   cudaGetSymbolAddress((void**)&dg,   g_deg);
    unsigned* gbuf; cudaGetSymbolAddress((void**)&gbuf, g_g);
    unsigned* hbuf16; cudaGetSymbolAddress((void**)&hbuf16, g_h);
    float*    hbuf; cudaGetSymbolAddress((void**)&hbuf, g_hbuf);

    // CSR build + dis + graph starts
    cudaMemsetAsync(dg, 0, N_NODES * sizeof(int));
    k_bucket8<<<(N_EDGES / 8 + 255) / 256, 256>>>(src, dst);
    k_dis_starts<<<(N_NODES + 255) / 256, 256>>>(batch);

    const int gemm_grid = (N_NODES + 63) / 64;           // 157
    const int agg_grid  = (N_NODES * 32 + 255) / 256;    // warp per node

    // layer 0 (fp32 X input, fused conversion)
    k_gemm<true><<<gemm_grid, 512>>>((const void*)x, W0, gbuf);
    k_agg<<<agg_grid, 256>>>(gbuf, b0, hbuf16, hbuf, 1);
    // layer 1
    k_gemm<false><<<gemm_grid, 512>>>((const void*)hbuf16, W1, gbuf);
    k_agg<<<agg_grid, 256>>>(gbuf, b1, hbuf16, hbuf, 1);
    // layer 2
    k_gemm<false><<<gemm_grid, 512>>>((const void*)hbuf16, W2, gbuf);
    k_agg<<<agg_grid, 256>>>(gbuf, b2, hbuf16, hbuf, 0);

    // mean pool
    k_pool<<<NGRAPH, FDIM>>>(hbuf, out);
}

// round 10
// speedup vs baseline: 1.1806x; 1.1806x over previous
#include <cuda_runtime.h>
#include <cuda_fp16.h>
#include <cstdint>

#define N_NODES 10000
#define N_EDGES 640000
#define FDIM    128
#define NGRAPH  64
#define MAXD    192

// ---------------- device scratch (no allocation allowed) ----------------
__device__ int    g_deg[N_NODES];
__device__ float  g_dis[N_NODES];
__device__ __align__(16) int g_bucket[N_NODES * MAXD];   // per-dst neighbor lists
__device__ __align__(128) __half g_gbuf[N_NODES * FDIM]; // GEMM out, dis-prescaled
__device__ __align__(128) __half g_h16[N_NODES * FDIM];  // agg out fp16 (layers 0,1)
__device__ float  g_hbuf[N_NODES * FDIM];                // agg out fp32 (layer 2)
__device__ int    g_starts[NGRAPH + 1];

// ---------------- one-pass bucket CSR: 8 edges per thread ----------------
__global__ void k_bucket8(const int* __restrict__ src, const int* __restrict__ dst) {
    int i = blockIdx.x * blockDim.x + threadIdx.x;
    if (i >= N_EDGES / 8) return;
    int4 s0 = ((const int4*)src)[i * 2 + 0];
    int4 s1 = ((const int4*)src)[i * 2 + 1];
    int4 d0 = ((const int4*)dst)[i * 2 + 0];
    int4 d1 = ((const int4*)dst)[i * 2 + 1];
    int p;
    p = atomicAdd(&g_deg[d0.x], 1); if (p < MAXD) g_bucket[d0.x * MAXD + p] = s0.x;
    p = atomicAdd(&g_deg[d0.y], 1); if (p < MAXD) g_bucket[d0.y * MAXD + p] = s0.y;
    p = atomicAdd(&g_deg[d0.z], 1); if (p < MAXD) g_bucket[d0.z * MAXD + p] = s0.z;
    p = atomicAdd(&g_deg[d0.w], 1); if (p < MAXD) g_bucket[d0.w * MAXD + p] = s0.w;
    p = atomicAdd(&g_deg[d1.x], 1); if (p < MAXD) g_bucket[d1.x * MAXD + p] = s1.x;
    p = atomicAdd(&g_deg[d1.y], 1); if (p < MAXD) g_bucket[d1.y * MAXD + p] = s1.y;
    p = atomicAdd(&g_deg[d1.z], 1); if (p < MAXD) g_bucket[d1.z * MAXD + p] = s1.z;
    p = atomicAdd(&g_deg[d1.w], 1); if (p < MAXD) g_bucket[d1.w * MAXD + p] = s1.w;
}

// dis = rsqrt(deg+1); also graph-boundary starts (batch is sorted)
__global__ void k_dis_starts(const int* __restrict__ batch) {
    int n = blockIdx.x * blockDim.x + threadIdx.x;
    if (n >= N_NODES) return;
    g_dis[n] = rsqrtf((float)g_deg[n] + 1.0f);
    int b1 = batch[n];
    if (n == 0) {
        for (int b = 0; b <= b1; b++) g_starts[b] = 0;
    } else {
        int b0 = batch[n - 1];
        for (int b = b0 + 1; b <= b1; b++) g_starts[b] = n;
    }
    if (n == N_NODES - 1) {
        for (int b = b1 + 1; b <= NGRAPH; b++) g_starts[b] = N_NODES;
    }
}

// ---------------- HMMA GEMM: OUT[n][:] = half( dis[n] * (A[n][:] @ W) ) ----------------
__device__ __forceinline__ int swz_g(int row, int col8) {
    return row * FDIM + ((col8 ^ (row & 7)) << 3);
}
__device__ __forceinline__ int swz_h(int row, int col) {
    return row * FDIM + (((col >> 3) ^ (row & 7)) << 3) + (col & 7);
}

template<bool F32IN>
__global__ __launch_bounds__(512) void k_gemm(const void* __restrict__ Ap,
                                              const float* __restrict__ Wf,
                                              __half* __restrict__ OUT) {
    __shared__ __half Wsh[FDIM * FDIM];   // 32 KB
    __shared__ __half Ash[64 * FDIM];     // 16 KB
    int tid  = threadIdx.x;
    int lane = tid & 31;
    int warp = tid >> 5;
    int row0 = blockIdx.x * 64;

    #pragma unroll
    for (int i = 0; i < 8; i++) {
        int idx = tid + i * 512;
        int r   = idx >> 5;
        int c   = (idx & 31) * 4;
        float4 v = ((const float4*)Wf)[idx];
        uint2 h;
        *(__half2*)&h.x = __floats2half2_rn(v.x, v.y);
        *(__half2*)&h.y = __floats2half2_rn(v.z, v.w);
        *(uint2*)&Wsh[swz_h(r, c)] = h;
    }
    if (F32IN) {
        const float* A = (const float*)Ap;
        #pragma unroll
        for (int i = 0; i < 4; i++) {
            int idx = tid + i * 512;
            int r   = idx >> 5;
            int c   = (idx & 31) * 4;
            int gr  = row0 + r;
            float4 v = make_float4(0.f, 0.f, 0.f, 0.f);
            if (gr < N_NODES) v = *(const float4*)&A[gr * FDIM + c];
            uint2 h;
            *(__half2*)&h.x = __floats2half2_rn(v.x, v.y);
            *(__half2*)&h.y = __floats2half2_rn(v.z, v.w);
            *(uint2*)&Ash[swz_h(r, c)] = h;
        }
    } else {
        const __half* A = (const __half*)Ap;
        #pragma unroll
        for (int i = 0; i < 2; i++) {
            int idx = tid + i * 512;        // 0..1023
            int r   = idx >> 4;
            int c8  = idx & 15;
            int gr  = row0 + r;
            uint4 v = make_uint4(0, 0, 0, 0);
            if (gr < N_NODES) v = ((const uint4*)A)[gr * 16 + c8];
            *(uint4*)&Ash[swz_g(r, c8)] = v;
        }
    }
    __syncthreads();

    int rw = (warp >> 2) * 16;
    int cw = (warp & 3) * 32;

    float acc[4][4];
    #pragma unroll
    for (int nt = 0; nt < 4; nt++)
        #pragma unroll
        for (int c = 0; c < 4; c++) acc[nt][c] = 0.f;

    int m  = lane >> 3;
    int l7 = lane & 7;

    #pragma unroll
    for (int kk = 0; kk < 8; kk++) {
        int k0 = kk * 16;
        uint32_t a0, a1, a2, a3;
        {
            int rl = rw + ((m & 1) << 3) + l7;
            int c8 = (k0 >> 3) + (m >> 1);
            uint32_t addr = (uint32_t)__cvta_generic_to_shared(&Ash[swz_g(rl, c8)]);
            asm volatile("ldmatrix.sync.aligned.m8n8.x4.shared.b16 {%0,%1,%2,%3}, [%4];"
                         : "=r"(a0), "=r"(a1), "=r"(a2), "=r"(a3) : "r"(addr));
        }
        #pragma unroll
        for (int nb = 0; nb < 2; nb++) {
            int n0 = cw + nb * 16;
            uint32_t b0, b1, b2, b3;
            {
                int rl = k0 + ((m & 1) << 3) + l7;
                int c8 = (n0 >> 3) + (m >> 1);
                uint32_t addr = (uint32_t)__cvta_generic_to_shared(&Wsh[swz_g(rl, c8)]);
                asm volatile("ldmatrix.sync.aligned.m8n8.x4.trans.shared.b16 {%0,%1,%2,%3}, [%4];"
                             : "=r"(b0), "=r"(b1), "=r"(b2), "=r"(b3) : "r"(addr));
            }
            float* c0 = acc[nb * 2];
            float* c1 = acc[nb * 2 + 1];
            asm volatile("mma.sync.aligned.m16n8k16.row.col.f32.f16.f16.f32 "
                         "{%0,%1,%2,%3}, {%4,%5,%6,%7}, {%8,%9}, {%0,%1,%2,%3};"
                         : "+f"(c0[0]), "+f"(c0[1]), "+f"(c0[2]), "+f"(c0[3])
                         : "r"(a0), "r"(a1), "r"(a2), "r"(a3), "r"(b0), "r"(b1));
            asm volatile("mma.sync.aligned.m16n8k16.row.col.f32.f16.f16.f32 "
                         "{%0,%1,%2,%3}, {%4,%5,%6,%7}, {%8,%9}, {%0,%1,%2,%3};"
                         : "+f"(c1[0]), "+f"(c1[1]), "+f"(c1[2]), "+f"(c1[3])
                         : "r"(a0), "r"(a1), "r"(a2), "r"(a3), "r"(b2), "r"(b3));
        }
    }

    int gid  = lane >> 2;
    int tid4 = lane & 3;
    int r1 = row0 + rw + gid;
    int r2 = r1 + 8;
    float d1 = (r1 < N_NODES) ? g_dis[r1] : 0.f;
    float d2 = (r2 < N_NODES) ? g_dis[r2] : 0.f;
    #pragma unroll
    for (int nt = 0; nt < 4; nt++) {
        int col = cw + nt * 8 + tid4 * 2;
        if (r1 < N_NODES)
            *(__half2*)&OUT[r1 * FDIM + col] = __floats2half2_rn(acc[nt][0] * d1, acc[nt][1] * d1);
        if (r2 < N_NODES)
            *(__half2*)&OUT[r2 * FDIM + col] = __floats2half2_rn(acc[nt][2] * d2, acc[nt][3] * d2);
    }
}

// ---------------- aggregation: H[n] = act(dis[n]*(sum g[src] + g[n]) + b) ----------------
// WARP per node, but each LDG.128 fetches 2 edges (half-warp h handles edges
// i+4h..i+4h+3 of each 8-edge chunk; lane covers feature chunk (lane&15)*8..+8).
// Final half-combine via 8x SHFL.XOR(16). fp16 tree depth 2 per chunk.
#define H2(u) (*(__half2*)&(u))

__device__ __forceinline__ void add_h4(float* acc, uint4 v) {
    float2 t;
    t = __half22float2(H2(v.x)); acc[0] += t.x; acc[1] += t.y;
    t = __half22float2(H2(v.y)); acc[2] += t.x; acc[3] += t.y;
    t = __half22float2(H2(v.z)); acc[4] += t.x; acc[5] += t.y;
    t = __half22float2(H2(v.w)); acc[6] += t.x; acc[7] += t.y;
}

__global__ __launch_bounds__(256) void k_agg(const __half* __restrict__ Gm,
                                             const float* __restrict__ bias,
                                             __half* __restrict__ H16,
                                             float* __restrict__ Hf,
                                             int relu) {
    int n    = (blockIdx.x * blockDim.x + threadIdx.x) >> 5;
    int lane = threadIdx.x & 31;
    if (n >= N_NODES) return;
    int hw  = lane >> 4;                 // half-warp id 0/1
    int fl  = lane & 15;                 // feature chunk (uint4 index in row)
    int deg = g_deg[n];
    if (deg > MAXD) deg = MAXD;
    const uint4* G4 = (const uint4*)Gm;  // row = 16 uint4
    const int* bk = g_bucket + n * MAXD;

    float acc[8] = {0.f, 0.f, 0.f, 0.f, 0.f, 0.f, 0.f, 0.f};
    if (hw == 0) add_h4(acc, G4[n * 16 + fl]);     // self contribution once

    int i = 0;
    for (; i + 8 <= deg; i += 8) {
        // broadcast int4 within each half-warp (2 addresses, usually same line)
        int4 idx = *(const int4*)(bk + i + hw * 4);
        uint4 v0 = G4[idx.x * 16 + fl];
        uint4 v1 = G4[idx.y * 16 + fl];
        uint4 v2 = G4[idx.z * 16 + fl];
        uint4 v3 = G4[idx.w * 16 + fl];
        __half2 s0 = __hadd2(__hadd2(H2(v0.x), H2(v1.x)), __hadd2(H2(v2.x), H2(v3.x)));
        __half2 s1 = __hadd2(__hadd2(H2(v0.y), H2(v1.y)), __hadd2(H2(v2.y), H2(v3.y)));
        __half2 s2 = __hadd2(__hadd2(H2(v0.z), H2(v1.z)), __hadd2(H2(v2.z), H2(v3.z)));
        __half2 s3 = __hadd2(__hadd2(H2(v0.w), H2(v1.w)), __hadd2(H2(v2.w), H2(v3.w)));
        float2 t;
        t = __half22float2(s0); acc[0] += t.x; acc[1] += t.y;
        t = __half22float2(s1); acc[2] += t.x; acc[3] += t.y;
        t = __half22float2(s2); acc[4] += t.x; acc[5] += t.y;
        t = __half22float2(s3); acc[6] += t.x; acc[7] += t.y;
    }
    // pairs: each half takes one edge
    for (; i + 2 <= deg; i += 2) {
        int idx = bk[i + hw];
        add_h4(acc, G4[idx * 16 + fl]);
    }
    // final odd edge: half 0 only
    if (i < deg && hw == 0) {
        add_h4(acc, G4[bk[i] * 16 + fl]);
    }

    // merge half-warps (lane L <-> L^16 hold same feature chunk)
    #pragma unroll
    for (int j = 0; j < 8; j++)
        acc[j] += __shfl_xor_sync(0xffffffffu, acc[j], 16);

    if (hw == 0) {
        float d = g_dis[n];
        float4 bb0 = ((const float4*)bias)[fl * 2];
        float4 bb1 = ((const float4*)bias)[fl * 2 + 1];
        float o[8];
        o[0] = d * acc[0] + bb0.x;  o[1] = d * acc[1] + bb0.y;
        o[2] = d * acc[2] + bb0.z;  o[3] = d * acc[3] + bb0.w;
        o[4] = d * acc[4] + bb1.x;  o[5] = d * acc[5] + bb1.y;
        o[6] = d * acc[6] + bb1.z;  o[7] = d * acc[7] + bb1.w;
        if (relu) {
            #pragma unroll
            for (int j = 0; j < 8; j++) o[j] = fmaxf(o[j], 0.f);
            uint4 h;
            *(__half2*)&h.x = __floats2half2_rn(o[0], o[1]);
            *(__half2*)&h.y = __floats2half2_rn(o[2], o[3]);
            *(__half2*)&h.z = __floats2half2_rn(o[4], o[5]);
            *(__half2*)&h.w = __floats2half2_rn(o[6], o[7]);
            ((uint4*)H16)[n * 16 + fl] = h;
        } else {
            ((float4*)Hf)[n * 32 + fl * 2]     = make_float4(o[0], o[1], o[2], o[3]);
            ((float4*)Hf)[n * 32 + fl * 2 + 1] = make_float4(o[4], o[5], o[6], o[7]);
        }
    }
}

// ---------------- mean pool: one block per graph, 4 warps split rows ----------------
__global__ __launch_bounds__(128) void k_pool(const float* __restrict__ H,
                                              float* __restrict__ out) {
    __shared__ float red[4][FDIM];
    int g    = blockIdx.x;
    int lane = threadIdx.x & 31;
    int warp = threadIdx.x >> 5;
    int s = g_starts[g];
    int e = g_starts[g + 1];
    float4 acc = make_float4(0.f, 0.f, 0.f, 0.f);
    for (int n = s + warp; n < e; n += 4) {
        float4 v = ((const float4*)H)[n * 32 + lane];
        acc.x += v.x; acc.y += v.y; acc.z += v.z; acc.w += v.w;
    }
    *(float4*)&red[warp][lane * 4] = acc;
    __syncthreads();
    int t = threadIdx.x;
    float sum = red[0][t] + red[1][t] + red[2][t] + red[3][t];
    float cnt = (float)(e - s);
    out[g * FDIM + t] = sum / fmaxf(cnt, 1.0f);
}

// ---------------- launch ----------------
extern "C" void kernel_launch(void* const* d_in, const int* in_sizes, int n_in,
                              void* d_out, int out_size) {
    const float* x     = (const float*)d_in[0];
    const int*   ei    = (const int*)d_in[1];
    const int*   batch = (const int*)d_in[2];
    const float* W0    = (const float*)d_in[3];
    const float* b0    = (const float*)d_in[4];
    const float* W1    = (const float*)d_in[5];
    const float* b1    = (const float*)d_in[6];
    const float* W2    = (const float*)d_in[7];
    const float* b2    = (const float*)d_in[8];
    float* out = (float*)d_out;

    const int* src = ei;
    const int* dst = ei + N_EDGES;

    int*    dg;   cudaGetSymbolAddress((void**)&dg,   g_deg);
    __half* gbuf; cudaGetSymbolAddress((void**)&gbuf, g_gbuf);
    __half* h16;  cudaGetSymbolAddress((void**)&h16,  g_h16);
    float*  hbuf; cudaGetSymbolAddress((void**)&hbuf, g_hbuf);

    // CSR build + dis + graph starts
    cudaMemsetAsync(dg, 0, N_NODES * sizeof(int));
    k_bucket8<<<(N_EDGES / 8 + 255) / 256, 256>>>(src, dst);
    k_dis_starts<<<(N_NODES + 255) / 256, 256>>>(batch);

    const int gemm_grid = (N_NODES + 63) / 64;           // 157
    const int agg_grid  = (N_NODES * 32 + 255) / 256;    // warp per node

    // layer 0 (fp32 X input, fused conversion)
    k_gemm<true><<<gemm_grid, 512>>>((const void*)x, W0, gbuf);
    k_agg<<<agg_grid, 256>>>(gbuf, b0, h16, hbuf, 1);
    // layer 1
    k_gemm<false><<<gemm_grid, 512>>>((const void*)h16, W1, gbuf);
    k_agg<<<agg_grid, 256>>>(gbuf, b1, h16, hbuf, 1);
    // layer 2
    k_gemm<false><<<gemm_grid, 512>>>((const void*)h16, W2, gbuf);
    k_agg<<<agg_grid, 256>>>(gbuf, b2, h16, hbuf, 0);

    // mean pool
    k_pool<<<NGRAPH, FDIM>>>(hbuf, out);
}